// round 3
// baseline (speedup 1.0000x reference)
#include <cuda_runtime.h>

namespace {

constexpr int H = 64, W = 64, C = 256;
constexpr int NDY = 21, NDX = 21;
constexpr int CC = 16;                  // channels per smem chunk
constexpr int S1ROW = 72;               // in1 row: plane0 @0 (32 floats), plane1 @36
constexpr int S2ROW = 120;              // in2 row: plane0 @0 (52 floats), plane1 @68
constexpr int SM_FLOATS = CC * S1ROW + CC * S2ROW;  // 1152 + 1920 = 3072

__global__ void __launch_bounds__(32)
corr_kernel(const float* __restrict__ in1, const float* __restrict__ in2,
            float* __restrict__ out)
{
    __shared__ float sm[SM_FLOATS];
    float* s1 = sm;                 // [CC][2 planes of 32 (+pad)]
    float* s2 = sm + CC * S1ROW;    // [CC][2 planes of 52 (+pad)]

    const int h   = blockIdx.x;
    const int dyi = blockIdx.y;
    const int b   = blockIdx.z;
    const int t   = threadIdx.x;

    const int h2 = h + (dyi - 10) * 2;

    // out[b][dyi*21 + j][h][w]
    float* outp = out + (((long)b * (NDY * NDX) + (long)dyi * NDX) * H + h) * W;

    if (h2 < 0 || h2 >= H) {
        float4 z = make_float4(0.f, 0.f, 0.f, 0.f);
        for (int k = t; k < NDX * 16; k += 32) {       // 21 * 16 float4
            int j = k >> 4, i4 = k & 15;
            *(float4*)(outp + (long)j * (H * W) + 4 * i4) = z;
        }
        return;
    }

    // lane -> (u-tile, parity, j-group)
    const int bq = t & 3;           // u0 = 8*bq
    const int p  = (t >> 2) & 1;    // w parity
    const int jg = t >> 3;          // j0 = 5*jg
    const int u0 = bq * 8;
    const int j0 = jg * 5;

    const int offA = p * 36 + u0;            // + c*S1ROW
    const int offB = p * 68 + u0 + j0;       // + c*S2ROW

    float acc[6][8];
#pragma unroll
    for (int jj = 0; jj < 6; ++jj)
#pragma unroll
        for (int uu = 0; uu < 8; ++uu) acc[jj][uu] = 0.f;

    const float* g1 = in1 + ((long)b * C * H + h)  * W;
    const float* g2 = in2 + ((long)b * C * H + h2) * W;

    // zero-init s2 once (pad regions pos[0,10) and [42,52) stay zero forever)
    float4 z4 = make_float4(0.f, 0.f, 0.f, 0.f);
    for (int k = t; k < CC * S2ROW / 4; k += 32) ((float4*)s2)[k] = z4;

    for (int c0 = 0; c0 < C; c0 += CC) {
        __syncwarp();   // previous chunk's reads done; zero-init visible on first iter
        // ---- stage in1: CC rows x 16 float4, parity-split
#pragma unroll
        for (int it = 0; it < 8; ++it) {
            int idx = t + 32 * it;
            int c = idx >> 4, i4 = idx & 15;
            float4 v = *(const float4*)(g1 + (long)(c0 + c) * (H * W) + 4 * i4);
            *(float2*)(s1 + c * S1ROW      + 2 * i4) = make_float2(v.x, v.z);
            *(float2*)(s1 + c * S1ROW + 36 + 2 * i4) = make_float2(v.y, v.w);
        }
        // ---- stage in2: CC rows x 16 float4 -> pos 10..41 in each plane
#pragma unroll
        for (int it = 0; it < 8; ++it) {
            int idx = t + 32 * it;
            int c = idx >> 4, i4 = idx & 15;
            float4 v = *(const float4*)(g2 + (long)(c0 + c) * (H * W) + 4 * i4);
            *(float2*)(s2 + c * S2ROW + 10      + 2 * i4) = make_float2(v.x, v.z);
            *(float2*)(s2 + c * S2ROW + 68 + 10 + 2 * i4) = make_float2(v.y, v.w);
        }
        __syncwarp();

        // ---- compute: per channel 2x LDS.128 (A) + 13 scalar LDS (B) + 48 FMA
#pragma unroll 2
        for (int c = 0; c < CC; ++c) {
            const float* pa = s1 + c * S1ROW + offA;
            const float* pb = s2 + c * S2ROW + offB;
            float4 a0 = *(const float4*)pa;
            float4 a1 = *(const float4*)(pa + 4);
            float A[8] = {a0.x, a0.y, a0.z, a0.w, a1.x, a1.y, a1.z, a1.w};
            float Bv[13];
#pragma unroll
            for (int k = 0; k < 13; ++k) Bv[k] = pb[k];
#pragma unroll
            for (int jj = 0; jj < 6; ++jj)
#pragma unroll
                for (int uu = 0; uu < 8; ++uu)
                    acc[jj][uu] = fmaf(A[uu], Bv[uu + jj], acc[jj][uu]);
        }
    }

    __syncwarp();
    // ---- stage outputs [j][w] in smem (dup j's write identical values), coalesced store
    float* sout = sm;
    const float scale = 1.0f / 256.0f;
#pragma unroll
    for (int jj = 0; jj < 6; ++jj) {
        int j = j0 + jj;
#pragma unroll
        for (int uu = 0; uu < 8; ++uu)
            sout[j * 64 + p + 2 * (u0 + uu)] = acc[jj][uu] * scale;
    }
    __syncwarp();

    for (int k = t; k < NDX * 16; k += 32) {
        int j = k >> 4, i4 = k & 15;
        *(float4*)(outp + (long)j * (H * W) + 4 * i4) = *(float4*)(sout + j * 64 + 4 * i4);
    }
}

} // namespace

extern "C" void kernel_launch(void* const* d_in, const int* in_sizes, int n_in,
                              void* d_out, int out_size)
{
    const float* in1 = (const float*)d_in[0];
    const float* in2 = (const float*)d_in[1];
    float* out = (float*)d_out;
    dim3 grid(H, NDY, 8);
    corr_kernel<<<grid, 32>>>(in1, in2, out);
}